// round 1
// baseline (speedup 1.0000x reference)
#include <cuda_runtime.h>

// Problem constants (fixed by the dataset)
namespace {
constexpr int kB  = 8;
constexpr int kN  = 4096;
constexpr int kE  = 128;   // Din
constexpr int kF  = 256;   // Dout
constexpr int kNT = 32;    // n-tile per block
constexpr int kM  = 3 * kNT;  // 96 columns (m = nl*3 + i)

constexpr int A_S  = 100;  // a_s row stride (floats): 16B-aligned rows, conflict-free reads
constexpr int Y_S  = 100;  // y_s row stride
constexpr int MS_S = 260;  // staged weight-chunk row stride (e-major / c-major)

constexpr int R2_OFF      = kE * A_S;            // 12800 floats
constexpr int SMEM_FLOATS = R2_OFF + kF * Y_S;   // 12800 + 25600 = 38400
constexpr int SMEM_BYTES  = SMEM_FLOATS * 4;     // 153600 B
}

__global__ __launch_bounds__(256, 1)
void affine_vn_fused(const float* __restrict__ X, const float* __restrict__ J,
                     const float* __restrict__ Am, const float* __restrict__ Bm,
                     const float* __restrict__ Cm, const float* __restrict__ Wd,
                     float* __restrict__ out)
{
    extern __shared__ float sm[];
    float* a_s = sm;               // [128][A_S]   a-tile; later re-used as W chunk [32][MS_S]
    float* r2  = sm + R2_OFF;      // M chunk [64][MS_S], later y_s [256][Y_S]

    const int t  = threadIdx.x;
    const int b  = blockIdx.y;
    const int n0 = blockIdx.x * kNT;
    const int tx = t & 7;          // 8 m-groups of 12
    const int ty = t >> 3;         // 32 f-groups of 8
    const int fb = ty * 8;
    const int mb = tx * 12;        // 4 points x 3 components

    // ---------------- Phase 1: rotations + projections -> a_s[e][nl*3+i] ----------------
    #pragma unroll 4
    for (int it = 0; it < 16; ++it) {
        const int q  = it * 256 + t;
        const int e  = q & (kE - 1);   // consecutive lanes -> consecutive e (coalesced)
        const int nl = q >> 7;
        const size_t base = (size_t)(b * kN + n0 + nl) * kE + e;
        const float* xp = X + base * 3;
        const float* jp = J + base * 6;   // [3][2] layout: col0 at 0,2,4; col1 at 1,3,5
        const float x0 = xp[0], x1 = xp[1], x2 = xp[2];
        const float u0 = jp[0], u1 = jp[2], u2 = jp[4];
        const float v0 = jp[1], v1 = jp[3], v2 = jp[5];

        const float nn  = u0*u0 + u1*u1 + u2*u2;
        const float iv1 = rsqrtf(fmaxf(nn, 1e-24f));          // == 1/max(||u||,1e-12)
        const float b10 = u0*iv1, b11 = u1*iv1, b12 = u2*iv1;
        const float dp  = b10*v0 + b11*v1 + b12*v2;
        const float w0 = v0 - dp*b10, w1 = v1 - dp*b11, w2 = v2 - dp*b12;
        const float wn  = w0*w0 + w1*w1 + w2*w2;
        const float iv2 = rsqrtf(fmaxf(wn, 1e-24f));
        const float b20 = w0*iv2, b21 = w1*iv2, b22 = w2*iv2;
        const float b30 = b11*b22 - b12*b21;
        const float b31 = b12*b20 - b10*b22;
        const float b32 = b10*b21 - b11*b20;

        float* as = a_s + e * A_S + nl * 3;
        as[0] = x0*b10 + x1*b11 + x2*b12;
        as[1] = x0*b20 + x1*b21 + x2*b22;
        as[2] = x0*b30 + x1*b31 + x2*b32;
    }
    __syncthreads();

    // ---------------- Phase 2: Y = (A+B+C) @ a  (K = 128, chunks of 64) ----------------
    float acc[8][12];
    #pragma unroll
    for (int i = 0; i < 8; ++i)
        #pragma unroll
        for (int j = 0; j < 12; ++j) acc[i][j] = 0.0f;

    for (int kc = 0; kc < kE; kc += 64) {
        // stage Mcomb chunk [64 e][256 f] into r2 (e-major, stride MS_S)
        #pragma unroll 8
        for (int it = 0; it < 64; ++it) {
            const int q  = it * 256 + t;
            const int f  = q >> 6;
            const int el = q & 63;       // consecutive lanes -> consecutive e (coalesced LDG)
            const int gi = f * kE + kc + el;
            r2[el * MS_S + f] = Am[gi] + Bm[gi] + Cm[gi];
        }
        __syncthreads();

        #pragma unroll 4
        for (int el = 0; el < 64; ++el) {
            float mv[8];
            {
                const float4 m0 = *reinterpret_cast<const float4*>(r2 + el * MS_S + fb);
                const float4 m1 = *reinterpret_cast<const float4*>(r2 + el * MS_S + fb + 4);
                mv[0]=m0.x; mv[1]=m0.y; mv[2]=m0.z; mv[3]=m0.w;
                mv[4]=m1.x; mv[5]=m1.y; mv[6]=m1.z; mv[7]=m1.w;
            }
            float av[12];
            {
                const float* ap = a_s + (kc + el) * A_S + mb;
                const float4 a0 = *reinterpret_cast<const float4*>(ap);
                const float4 a1 = *reinterpret_cast<const float4*>(ap + 4);
                const float4 a2 = *reinterpret_cast<const float4*>(ap + 8);
                av[0]=a0.x; av[1]=a0.y; av[2]=a0.z;  av[3]=a0.w;
                av[4]=a1.x; av[5]=a1.y; av[6]=a1.z;  av[7]=a1.w;
                av[8]=a2.x; av[9]=a2.y; av[10]=a2.z; av[11]=a2.w;
            }
            #pragma unroll
            for (int ff = 0; ff < 8; ++ff)
                #pragma unroll
                for (int mm = 0; mm < 12; ++mm)
                    acc[ff][mm] = fmaf(mv[ff], av[mm], acc[ff][mm]);
        }
        __syncthreads();   // protect next chunk's overwrite of r2
    }

    // write Y tile into y_s (r2 region; m_s is dead after the sync above)
    #pragma unroll
    for (int ff = 0; ff < 8; ++ff) {
        float* yp = r2 + (fb + ff) * Y_S + mb;
        *reinterpret_cast<float4*>(yp)     = make_float4(acc[ff][0], acc[ff][1], acc[ff][2],  acc[ff][3]);
        *reinterpret_cast<float4*>(yp + 4) = make_float4(acc[ff][4], acc[ff][5], acc[ff][6],  acc[ff][7]);
        *reinterpret_cast<float4*>(yp + 8) = make_float4(acc[ff][8], acc[ff][9], acc[ff][10], acc[ff][11]);
    }
    __syncthreads();

    // ---------------- Phase 3: d = W @ y  (K = 256, chunks of 32; W staged in a_s region) ----
    float dcc[8][12];
    #pragma unroll
    for (int i = 0; i < 8; ++i)
        #pragma unroll
        for (int j = 0; j < 12; ++j) dcc[i][j] = 0.0f;

    for (int kc = 0; kc < kF; kc += 32) {
        #pragma unroll 8
        for (int it = 0; it < 32; ++it) {
            const int q  = it * 256 + t;
            const int o  = q >> 5;
            const int cl = q & 31;       // consecutive lanes -> consecutive c (coalesced LDG)
            a_s[cl * MS_S + o] = Wd[o * kF + kc + cl];
        }
        __syncthreads();

        #pragma unroll 4
        for (int cl = 0; cl < 32; ++cl) {
            float wv[8];
            {
                const float4 w0 = *reinterpret_cast<const float4*>(a_s + cl * MS_S + fb);
                const float4 w1 = *reinterpret_cast<const float4*>(a_s + cl * MS_S + fb + 4);
                wv[0]=w0.x; wv[1]=w0.y; wv[2]=w0.z; wv[3]=w0.w;
                wv[4]=w1.x; wv[5]=w1.y; wv[6]=w1.z; wv[7]=w1.w;
            }
            float yv[12];
            {
                const float* yp = r2 + (kc + cl) * Y_S + mb;
                const float4 y0 = *reinterpret_cast<const float4*>(yp);
                const float4 y1 = *reinterpret_cast<const float4*>(yp + 4);
                const float4 y2 = *reinterpret_cast<const float4*>(yp + 8);
                yv[0]=y0.x; yv[1]=y0.y; yv[2]=y0.z;  yv[3]=y0.w;
                yv[4]=y1.x; yv[5]=y1.y; yv[6]=y1.z;  yv[7]=y1.w;
                yv[8]=y2.x; yv[9]=y2.y; yv[10]=y2.z; yv[11]=y2.w;
            }
            #pragma unroll
            for (int ff = 0; ff < 8; ++ff)
                #pragma unroll
                for (int mm = 0; mm < 12; ++mm)
                    dcc[ff][mm] = fmaf(wv[ff], yv[mm], dcc[ff][mm]);
        }
        __syncthreads();
    }

    // ---------------- Epilogue: VN-LeakyReLU + store [B, F, 3, N] ----------------
    #pragma unroll
    for (int ff = 0; ff < 8; ++ff) {
        const int o = fb + ff;
        float xv[12];
        {
            const float* yp = r2 + o * Y_S + mb;
            const float4 y0 = *reinterpret_cast<const float4*>(yp);
            const float4 y1 = *reinterpret_cast<const float4*>(yp + 4);
            const float4 y2 = *reinterpret_cast<const float4*>(yp + 8);
            xv[0]=y0.x; xv[1]=y0.y; xv[2]=y0.z;  xv[3]=y0.w;
            xv[4]=y1.x; xv[5]=y1.y; xv[6]=y1.z;  xv[7]=y1.w;
            xv[8]=y2.x; xv[9]=y2.y; xv[10]=y2.z; xv[11]=y2.w;
        }
        float res[12];
        #pragma unroll
        for (int nq = 0; nq < 4; ++nq) {
            const float X0 = xv[nq*3+0], X1 = xv[nq*3+1], X2 = xv[nq*3+2];
            const float D0 = dcc[ff][nq*3+0], D1 = dcc[ff][nq*3+1], D2 = dcc[ff][nq*3+2];
            const float dot = X0*D0 + X1*D1 + X2*D2;
            const float dsq = D0*D0 + D1*D1 + D2*D2;
            // out = x                         if dot >= 0
            //     = x - 0.8*dot/(dsq+eps)*d   if dot <  0
            const float s = (dot >= 0.0f) ? 0.0f : 0.8f * dot * __fdividef(1.0f, dsq + 1e-6f);
            res[nq*3+0] = X0 - s * D0;
            res[nq*3+1] = X1 - s * D1;
            res[nq*3+2] = X2 - s * D2;
        }
        const size_t ob = ((size_t)(b * kF + o) * 3) * kN + n0 + tx * 4;
        #pragma unroll
        for (int i = 0; i < 3; ++i) {
            const float4 v = make_float4(res[0+i], res[3+i], res[6+i], res[9+i]);
            *reinterpret_cast<float4*>(out + ob + (size_t)i * kN) = v;
        }
    }
}

extern "C" void kernel_launch(void* const* d_in, const int* in_sizes, int n_in,
                              void* d_out, int out_size) {
    (void)in_sizes; (void)n_in; (void)out_size;
    const float* X  = (const float*)d_in[0];
    const float* J  = (const float*)d_in[1];
    const float* Am = (const float*)d_in[2];
    const float* Bm = (const float*)d_in[3];
    const float* Cm = (const float*)d_in[4];
    const float* Wd = (const float*)d_in[5];
    // d_in[6] = "device" scalar, unused
    float* out = (float*)d_out;

    cudaFuncSetAttribute(affine_vn_fused,
                         cudaFuncAttributeMaxDynamicSharedMemorySize, SMEM_BYTES);
    dim3 grid(kN / kNT, kB);
    affine_vn_fused<<<grid, 256, SMEM_BYTES>>>(X, J, Am, Bm, Cm, Wd, out);
}